// round 1
// baseline (speedup 1.0000x reference)
#include <cuda_runtime.h>
#include <cstdint>

// Problem shape (fixed per reference)
#define N_CASES 6
#define ROWS 16384
#define COLS 4096
#define SLAB_ELEMS ((long long)ROWS * COLS)          // 67,108,864 floats
#define SLAB_VEC4  (SLAB_ELEMS / 4)                  // 16,777,216 float4

__global__ void select_copy_kernel(const float* __restrict__ x,
                                   const float* __restrict__ fingerprints,
                                   const float* __restrict__ cached_outputs,
                                   float* __restrict__ out) {
    __shared__ int s_idx;

    // Every block independently computes the selected index (28 loads; these
    // hit L2 after the first block, essentially free vs. the 512 MiB stream).
    if (threadIdx.x == 0) {
        float p0 = x[0], p1 = x[1], p2 = x[2], p3 = x[3];
        int idx = 0;
        // First match wins; scan high->low and overwrite so the LOWEST
        // matching index survives. No match -> 0 (matches reference argmax).
        #pragma unroll
        for (int c = N_CASES - 1; c >= 0; --c) {
            const float* f = fingerprints + 4 * c;
            if (p0 == f[0] && p1 == f[1] && p2 == f[2] && p3 == f[3]) {
                idx = c;
            }
        }
        s_idx = idx;
    }
    __syncthreads();

    const float4* __restrict__ src =
        reinterpret_cast<const float4*>(cached_outputs + (long long)s_idx * SLAB_ELEMS);
    float4* __restrict__ dst = reinterpret_cast<float4*>(out);

    const long long stride = (long long)gridDim.x * blockDim.x;
    long long i = (long long)blockIdx.x * blockDim.x + threadIdx.x;

    // 4x unrolled grid-stride streaming copy: front-batches 4 independent
    // 128-bit loads per iteration for MLP, streaming cache hints both ways.
    long long end4 = SLAB_VEC4 - 3 * stride;
    for (; i < end4; i += 4 * stride) {
        float4 v0 = __ldcs(src + i);
        float4 v1 = __ldcs(src + i + stride);
        float4 v2 = __ldcs(src + i + 2 * stride);
        float4 v3 = __ldcs(src + i + 3 * stride);
        __stcs(dst + i,              v0);
        __stcs(dst + i + stride,     v1);
        __stcs(dst + i + 2 * stride, v2);
        __stcs(dst + i + 3 * stride, v3);
    }
    for (; i < SLAB_VEC4; i += stride) {
        __stcs(dst + i, __ldcs(src + i));
    }
}

extern "C" void kernel_launch(void* const* d_in, const int* in_sizes, int n_in,
                              void* d_out, int out_size) {
    const float* x              = (const float*)d_in[0];
    const float* fingerprints   = (const float*)d_in[1];
    const float* cached_outputs = (const float*)d_in[2];
    float* out = (float*)d_out;

    const int threads = 256;
    const int blocks = 148 * 8;  // full-chip, ~55 float4 iters/thread
    select_copy_kernel<<<blocks, threads>>>(x, fingerprints, cached_outputs, out);
}